// round 3
// baseline (speedup 1.0000x reference)
#include <cuda_runtime.h>
#include <cuda_bf16.h>

#define NB 32768          // batch
#define TSEQ 200
#define HD 4

// ---------------- scratch (static device globals; no allocation) ----------------
__device__ float g_w[480];                        // packed LSTM weights, 2 streams x 240
__device__ float g_xT[400 * NB];                  // x transposed: [k=s*200+t][b]
__device__ float g_hist[1600 * NB];               // layer-1 h history: [s*800 + t*4 + u][b]
__device__ float g_F[256 * NB];                   // concat(Hf, Lf) transposed
__device__ float g_z1[80 * NB];                   // tanh(W1 z + b1) transposed
__device__ float g_other[40 * NB];                // x_flat @ Wp.T + bp transposed

// ---------------- math helpers ----------------
__device__ __forceinline__ float sigf(float x) {
    float e = __expf(-x);
    return __fdividef(1.0f, 1.0f + e);
}
__device__ __forceinline__ float tanh_acc(float x) {
    float e = __expf(-2.0f * x);
    return __fdividef(1.0f - e, 1.0f + e);
}
__device__ __forceinline__ unsigned long long ffma2(unsigned long long a,
                                                    unsigned long long b,
                                                    unsigned long long c) {
    unsigned long long d;
    asm("fma.rn.f32x2 %0, %1, %2, %3;" : "=l"(d) : "l"(a), "l"(b), "l"(c));
    return d;
}
union F2U { unsigned long long u; float2 f; };

// ---------------- weight prep: pack + pre-sum biases ----------------
struct WPtrs { const float* p[16]; };

__global__ void prep_kernel(WPtrs w) {
    // per stream layout: [0:16) Wih0, [16:80) Whh0, [80:96) b0=bih0+bhh0,
    //                    [96:160) Wih1, [160:224) Whh1, [224:240) b1=bih1+bhh1
    for (int i = threadIdx.x; i < 480; i += blockDim.x) {
        int s = i / 240, o = i % 240;
        const float* const* q = &w.p[s * 8];
        float v;
        if      (o < 16)  v = q[0][o];
        else if (o < 80)  v = q[1][o - 16];
        else if (o < 96)  v = q[2][o - 80] + q[3][o - 80];
        else if (o < 160) v = q[4][o - 96];
        else if (o < 224) v = q[5][o - 160];
        else              v = q[6][o - 224] + q[7][o - 224];
        g_w[i] = v;
    }
}

// ---------------- transpose x[b][400] -> xT[400][b] ----------------
__global__ void transpose_x(const float* __restrict__ x) {
    __shared__ float tile[32][33];
    int bi = blockIdx.x * 32, ki = blockIdx.y * 32;
    int tx = threadIdx.x, ty = threadIdx.y;   // (32,8)
#pragma unroll
    for (int i = 0; i < 32; i += 8) {
        int k = ki + tx, b = bi + ty + i;
        tile[ty + i][tx] = (k < 400) ? x[b * 400 + k] : 0.f;
    }
    __syncthreads();
#pragma unroll
    for (int i = 0; i < 32; i += 8) {
        int k = ki + ty + i, b = bi + tx;
        if (k < 400) g_xT[k * NB + b] = tile[tx][ty + i];
    }
}

// ---------------- fused 2-layer LSTM, thread per (stream, batch element) ----------------
__global__ __launch_bounds__(128) void lstm_kernel() {
    __shared__ __align__(16) float sw[240];
    int p = blockIdx.x * 128 + threadIdx.x;   // 65536 threads; block is stream-uniform
    int s = p >> 15;
    int b = p & (NB - 1);

    for (int i = threadIdx.x; i < 240; i += 128) sw[i] = g_w[s * 240 + i];
    __syncthreads();

    float rWih0[16], rb0[16], rb1[16];
#pragma unroll
    for (int i = 0; i < 16; i++) { rWih0[i] = sw[i]; rb0[i] = sw[80 + i]; rb1[i] = sw[224 + i]; }
    const float4* Whh0 = (const float4*)&sw[16];
    const float4* Wih1 = (const float4*)&sw[96];
    const float4* Whh1 = (const float4*)&sw[160];

    float h0[4] = {0, 0, 0, 0}, c0[4] = {0, 0, 0, 0};
    float h1[4] = {0, 0, 0, 0}, c1[4] = {0, 0, 0, 0};

    const float* xp = g_xT + s * TSEQ * NB + b;
    float* hp = g_hist + s * 800 * NB + b;

    for (int t = 0; t < TSEQ; t++) {
        float xv = xp[t * NB];
        float g[16];
        // layer 0 gates: g = x*Wih0 + b0 + Whh0 @ h0
#pragma unroll
        for (int gi = 0; gi < 16; gi++) {
            float4 w = Whh0[gi];
            float a = fmaf(xv, rWih0[gi], rb0[gi]);
            a = fmaf(h0[0], w.x, a); a = fmaf(h0[1], w.y, a);
            a = fmaf(h0[2], w.z, a); a = fmaf(h0[3], w.w, a);
            g[gi] = a;
        }
#pragma unroll
        for (int u = 0; u < 4; u++) {
            float iv = sigf(g[u]), fv = sigf(g[4 + u]);
            float gv = tanh_acc(g[8 + u]), ov = sigf(g[12 + u]);
            c0[u] = fmaf(fv, c0[u], iv * gv);
            h0[u] = ov * tanh_acc(c0[u]);
        }
        // layer 1 gates: g = Wih1 @ h0 + b1 + Whh1 @ h1
#pragma unroll
        for (int gi = 0; gi < 16; gi++) {
            float4 wi = Wih1[gi], wh = Whh1[gi];
            float a = rb1[gi];
            a = fmaf(h0[0], wi.x, a); a = fmaf(h0[1], wi.y, a);
            a = fmaf(h0[2], wi.z, a); a = fmaf(h0[3], wi.w, a);
            a = fmaf(h1[0], wh.x, a); a = fmaf(h1[1], wh.y, a);
            a = fmaf(h1[2], wh.z, a); a = fmaf(h1[3], wh.w, a);
            g[gi] = a;
        }
#pragma unroll
        for (int u = 0; u < 4; u++) {
            float iv = sigf(g[u]), fv = sigf(g[4 + u]);
            float gv = tanh_acc(g[8 + u]), ov = sigf(g[12 + u]);
            c1[u] = fmaf(fv, c1[u], iv * gv);
            h1[u] = ov * tanh_acc(c1[u]);
            hp[(t * 4 + u) * NB] = h1[u];
        }
    }
}

// ---------------- generic C[j][b] = act(W[j][:] . X[:][b] + bias[j]) ----------------
// X/C chosen by selector so no device addresses are needed on the host side.
// BM=64 x BN=128 tile, BK=16, 256 threads, packed f32x2 FMAs over batch pairs.
#define BM 64
#define BN 128
#define BK 16

// selectors
#define SEL_X_HIST0 0
#define SEL_X_HIST1 1
#define SEL_X_F     2
#define SEL_X_XT    3
#define SEL_C_F0    0
#define SEL_C_F1    1
#define SEL_C_Z1    2
#define SEL_C_OTHER 3

__global__ __launch_bounds__(256) void gemm_act(const float* __restrict__ W,
                                                const float* __restrict__ bias,
                                                int selX, int selC,
                                                int M, int K, int act) {
    const float* X = (selX == SEL_X_HIST0) ? g_hist
                   : (selX == SEL_X_HIST1) ? g_hist + 800 * NB
                   : (selX == SEL_X_F)     ? g_F
                                           : g_xT;
    float* C = (selC == SEL_C_F0) ? g_F
             : (selC == SEL_C_F1) ? g_F + 128 * NB
             : (selC == SEL_C_Z1) ? g_z1
                                  : g_other;

    __shared__ __align__(16) float2 Ws2[BK][BM];   // weight duplicated into both lanes
    __shared__ __align__(16) float  Xs[BK][BN];

    int tid = threadIdx.x;
    int b0 = blockIdx.x * BN;
    int j0 = blockIdx.y * BM;
    int tx = tid & 15;        // 16 b-groups of 8
    int ty = tid >> 4;        // 16 j-groups of 4

    unsigned long long acc[4][4];
#pragma unroll
    for (int i = 0; i < 4; i++)
#pragma unroll
        for (int p = 0; p < 4; p++) acc[i][p] = 0ull;

    int wrow = tid >> 2;              // 0..63
    int wc4  = (tid & 3) << 2;        // 0,4,8,12
    int xr   = tid >> 5;              // 0..7
    int xc   = (tid & 31) << 2;       // 0..124

    for (int k0 = 0; k0 < K; k0 += BK) {
        float4 w4 = make_float4(0.f, 0.f, 0.f, 0.f);
        if (j0 + wrow < M)
            w4 = *(const float4*)&W[(j0 + wrow) * K + k0 + wc4];
        Ws2[wc4 + 0][wrow] = make_float2(w4.x, w4.x);
        Ws2[wc4 + 1][wrow] = make_float2(w4.y, w4.y);
        Ws2[wc4 + 2][wrow] = make_float2(w4.z, w4.z);
        Ws2[wc4 + 3][wrow] = make_float2(w4.w, w4.w);
        *(float4*)&Xs[xr][xc]     = *(const float4*)&X[(k0 + xr) * NB + b0 + xc];
        *(float4*)&Xs[xr + 8][xc] = *(const float4*)&X[(k0 + xr + 8) * NB + b0 + xc];
        __syncthreads();
#pragma unroll
        for (int kk = 0; kk < BK; kk++) {
            ulonglong2 wA = *(const ulonglong2*)&Ws2[kk][ty * 4];
            ulonglong2 wB = *(const ulonglong2*)&Ws2[kk][ty * 4 + 2];
            ulonglong2 xA = *(const ulonglong2*)&Xs[kk][tx * 8];
            ulonglong2 xB = *(const ulonglong2*)&Xs[kk][tx * 8 + 4];
            unsigned long long wv[4] = {wA.x, wA.y, wB.x, wB.y};
            unsigned long long xv[4] = {xA.x, xA.y, xB.x, xB.y};
#pragma unroll
            for (int i = 0; i < 4; i++)
#pragma unroll
                for (int p = 0; p < 4; p++)
                    acc[i][p] = ffma2(wv[i], xv[p], acc[i][p]);
        }
        __syncthreads();
    }

    int bb = b0 + tx * 8;
#pragma unroll
    for (int i = 0; i < 4; i++) {
        int j = j0 + ty * 4 + i;
        if (j >= M) continue;
        float bj = bias[j];
        float o[8];
#pragma unroll
        for (int p = 0; p < 4; p++) {
            F2U u; u.u = acc[i][p];
            o[2 * p]     = u.f.x + bj;
            o[2 * p + 1] = u.f.y + bj;
        }
        if (act) {
#pragma unroll
            for (int e = 0; e < 8; e++) o[e] = tanh_acc(o[e]);
        }
        float4 v0 = make_float4(o[0], o[1], o[2], o[3]);
        float4 v1 = make_float4(o[4], o[5], o[6], o[7]);
        *(float4*)&C[j * NB + bb]     = v0;
        *(float4*)&C[j * NB + bb + 4] = v1;
    }
}

// ---------------- tail MLP: z2 = tanh(W2 z1 + b2); out = sigmoid(W3.[z2,other]+b3) ----------------
__global__ __launch_bounds__(256) void tail_kernel(const float* __restrict__ W2,
                                                   const float* __restrict__ b2,
                                                   const float* __restrict__ W3,
                                                   const float* __restrict__ b3,
                                                   float* __restrict__ out) {
    __shared__ float sW2[3200], sb2[40], sW3[80];
    __shared__ float sb3;
    int tid = threadIdx.x;
    for (int i = tid; i < 3200; i += 256) sW2[i] = W2[i];
    if (tid < 40) sb2[tid] = b2[tid];
    if (tid < 80) sW3[tid] = W3[tid];
    if (tid == 0) sb3 = b3[0];
    __syncthreads();

    int b = blockIdx.x * 256 + tid;
    float acc[40];
#pragma unroll
    for (int j = 0; j < 40; j++) acc[j] = sb2[j];
    for (int i = 0; i < 80; i++) {
        float v = g_z1[i * NB + b];
#pragma unroll
        for (int j = 0; j < 40; j++) acc[j] = fmaf(sW2[j * 80 + i], v, acc[j]);
    }
    float o = sb3;
#pragma unroll
    for (int j = 0; j < 40; j++) o = fmaf(sW3[j], tanh_acc(acc[j]), o);
#pragma unroll
    for (int i = 0; i < 40; i++) o = fmaf(sW3[40 + i], g_other[i * NB + b], o);
    out[b] = sigf(o);
}

// ---------------- launch ----------------
extern "C" void kernel_launch(void* const* d_in, const int* in_sizes, int n_in,
                              void* d_out, int out_size) {
    const float* x  = (const float*)d_in[0];
    WPtrs wp;
    for (int i = 0; i < 16; i++) wp.p[i] = (const float*)d_in[1 + i];
    const float* Wp = (const float*)d_in[17];
    const float* bp = (const float*)d_in[18];
    const float* WH = (const float*)d_in[19];
    const float* bH = (const float*)d_in[20];
    const float* WL = (const float*)d_in[21];
    const float* bL = (const float*)d_in[22];
    const float* W1 = (const float*)d_in[23];
    const float* b1 = (const float*)d_in[24];
    const float* W2 = (const float*)d_in[25];
    const float* b2 = (const float*)d_in[26];
    const float* W3 = (const float*)d_in[27];
    const float* b3 = (const float*)d_in[28];

    prep_kernel<<<1, 256>>>(wp);
    transpose_x<<<dim3(NB / 32, 13), dim3(32, 8)>>>(x);
    lstm_kernel<<<512, 128>>>();
    gemm_act<<<dim3(NB / BN, 2), 256>>>(WH, bH, SEL_X_HIST0, SEL_C_F0,   128, 800, 1);
    gemm_act<<<dim3(NB / BN, 2), 256>>>(WL, bL, SEL_X_HIST1, SEL_C_F1,   128, 800, 1);
    gemm_act<<<dim3(NB / BN, 2), 256>>>(W1, b1, SEL_X_F,     SEL_C_Z1,    80, 256, 1);
    gemm_act<<<dim3(NB / BN, 1), 256>>>(Wp, bp, SEL_X_XT,    SEL_C_OTHER, 40, 400, 0);
    tail_kernel<<<NB / 256, 256>>>(W2, b2, W3, b3, (float*)d_out);
}

// round 5
// speedup vs baseline: 1.7063x; 1.7063x over previous
#include <cuda_runtime.h>
#include <cuda_bf16.h>

#define NB 32768          // batch
#define TSEQ 200

// ---------------- scratch (static device globals; no allocation) ----------------
__device__ float g_w[480];                        // packed LSTM weights, 2 streams x 240
__device__ float g_xT[400 * NB];                  // x transposed: [k=s*200+t][b]
__device__ float g_hist[1600 * NB];               // layer-1 h history: [s*800 + t*4 + u][b]
__device__ float g_F[256 * NB];                   // concat(Hf, Lf) transposed
__device__ float g_z1[80 * NB];                   // tanh(W1 z + b1) transposed
__device__ float g_other[40 * NB];                // x_flat @ Wp.T + bp transposed

// ---------------- math helpers ----------------
__device__ __forceinline__ float tanhf_fast(float x) {
    float y;
    asm("tanh.approx.f32 %0, %1;" : "=f"(y) : "f"(x));
    return y;
}
__device__ __forceinline__ float sigf(float x) {
    return fmaf(0.5f, tanhf_fast(0.5f * x), 0.5f);
}
__device__ __forceinline__ float tanh_acc(float x) { return tanhf_fast(x); }

__device__ __forceinline__ unsigned long long ffma2(unsigned long long a,
                                                    unsigned long long b,
                                                    unsigned long long c) {
    unsigned long long d;
    asm("fma.rn.f32x2 %0, %1, %2, %3;" : "=l"(d) : "l"(a), "l"(b), "l"(c));
    return d;
}
union F2U { unsigned long long u; float2 f; };

// ---------------- weight prep: pack + pre-sum biases ----------------
struct WPtrs { const float* p[16]; };

__global__ void prep_kernel(WPtrs w) {
    for (int i = threadIdx.x; i < 480; i += blockDim.x) {
        int s = i / 240, o = i % 240;
        const float* const* q = &w.p[s * 8];
        float v;
        if      (o < 16)  v = q[0][o];
        else if (o < 80)  v = q[1][o - 16];
        else if (o < 96)  v = q[2][o - 80] + q[3][o - 80];
        else if (o < 160) v = q[4][o - 96];
        else if (o < 224) v = q[5][o - 160];
        else              v = q[6][o - 224] + q[7][o - 224];
        g_w[i] = v;
    }
}

// ---------------- transpose x[b][400] -> xT[400][b] ----------------
__global__ void transpose_x(const float* __restrict__ x) {
    __shared__ float tile[32][33];
    int bi = blockIdx.x * 32, ki = blockIdx.y * 32;
    int tx = threadIdx.x, ty = threadIdx.y;   // (32,8)
#pragma unroll
    for (int i = 0; i < 32; i += 8) {
        int k = ki + tx, b = bi + ty + i;
        tile[ty + i][tx] = (k < 400) ? x[b * 400 + k] : 0.f;
    }
    __syncthreads();
#pragma unroll
    for (int i = 0; i < 32; i += 8) {
        int k = ki + ty + i, b = bi + tx;
        if (k < 400) g_xT[k * NB + b] = tile[tx][ty + i];
    }
}

// ---------------- fused 2-layer LSTM, thread per (stream, batch element) ----------------
__global__ __launch_bounds__(128) void lstm_kernel() {
    __shared__ __align__(16) float sw[240];
    int p = blockIdx.x * 128 + threadIdx.x;
    int s = p >> 15;
    int b = p & (NB - 1);

    for (int i = threadIdx.x; i < 240; i += 128) sw[i] = g_w[s * 240 + i];
    __syncthreads();

    float rWih0[16], rb0[16], rb1[16];
#pragma unroll
    for (int i = 0; i < 16; i++) { rWih0[i] = sw[i]; rb0[i] = sw[80 + i]; rb1[i] = sw[224 + i]; }
    const float4* Whh0 = (const float4*)&sw[16];
    const float4* Wih1 = (const float4*)&sw[96];
    const float4* Whh1 = (const float4*)&sw[160];

    float h0[4] = {0, 0, 0, 0}, c0[4] = {0, 0, 0, 0};
    float h1[4] = {0, 0, 0, 0}, c1[4] = {0, 0, 0, 0};

    const float* xp = g_xT + s * TSEQ * NB + b;
    float* hp = g_hist + s * 800 * NB + b;

    for (int t = 0; t < TSEQ; t++) {
        float xv = xp[t * NB];
        float g[16];
#pragma unroll
        for (int gi = 0; gi < 16; gi++) {
            float4 w = Whh0[gi];
            float a = fmaf(xv, rWih0[gi], rb0[gi]);
            a = fmaf(h0[0], w.x, a); a = fmaf(h0[1], w.y, a);
            a = fmaf(h0[2], w.z, a); a = fmaf(h0[3], w.w, a);
            g[gi] = a;
        }
#pragma unroll
        for (int u = 0; u < 4; u++) {
            float iv = sigf(g[u]), fv = sigf(g[4 + u]);
            float gv = tanh_acc(g[8 + u]), ov = sigf(g[12 + u]);
            c0[u] = fmaf(fv, c0[u], iv * gv);
            h0[u] = ov * tanh_acc(c0[u]);
        }
#pragma unroll
        for (int gi = 0; gi < 16; gi++) {
            float4 wi = Wih1[gi], wh = Whh1[gi];
            float a = rb1[gi];
            a = fmaf(h0[0], wi.x, a); a = fmaf(h0[1], wi.y, a);
            a = fmaf(h0[2], wi.z, a); a = fmaf(h0[3], wi.w, a);
            a = fmaf(h1[0], wh.x, a); a = fmaf(h1[1], wh.y, a);
            a = fmaf(h1[2], wh.z, a); a = fmaf(h1[3], wh.w, a);
            g[gi] = a;
        }
#pragma unroll
        for (int u = 0; u < 4; u++) {
            float iv = sigf(g[u]), fv = sigf(g[4 + u]);
            float gv = tanh_acc(g[8 + u]), ov = sigf(g[12 + u]);
            c1[u] = fmaf(fv, c1[u], iv * gv);
            h1[u] = ov * tanh_acc(c1[u]);
            hp[(t * 4 + u) * NB] = h1[u];
        }
    }
}

// ---------------- GEMM core: C[j][b] = act(W[j][:] . X[:][b] + bias[j]) ----------------
// BM = TJ*16 rows x BN=128 batch, BK=16, 256 threads, thread tile TJ j x 8 b (f32x2 pairs).
#define BN 128
#define BK 16

template<int TJ>
__device__ __forceinline__ void gemm_body(const float* __restrict__ W,
                                          const float* __restrict__ bias,
                                          const float* __restrict__ X,
                                          float* __restrict__ C,
                                          int M, int K, int act, int b0) {
    constexpr int BMt = TJ * 16;
    constexpr int WPAD = 2;                      // float2 pad: row stride 16B-aligned, banks spread
    __shared__ __align__(16) float2 Ws2[BK][BMt + WPAD];
    __shared__ __align__(16) float  Xs[BK][BN];

    int tid = threadIdx.x;
    int tx = tid & 15;        // 16 batch groups of 8
    int ty = tid >> 4;        // 16 j groups of TJ

    unsigned long long acc[TJ][4];
#pragma unroll
    for (int i = 0; i < TJ; i++)
#pragma unroll
        for (int p = 0; p < 4; p++) acc[i][p] = 0ull;

    constexpr int TPR = BK / TJ;                 // threads per W row (2 or 4)
    int wrow = tid / TPR;                        // 0..BMt-1
    int wk   = (tid % TPR) * TJ;                 // k offset within tile
    int xr   = tid >> 4;                         // 0..15
    int xc   = (tid & 15) * 8;                   // 0..120

    for (int k0 = 0; k0 < K; k0 += BK) {
        // stage W (duplicated into float2 lanes)
#pragma unroll
        for (int q = 0; q < TJ / 4; q++) {
            float4 w4 = make_float4(0.f, 0.f, 0.f, 0.f);
            if (wrow < M)
                w4 = *(const float4*)&W[wrow * K + k0 + wk + q * 4];
            Ws2[wk + q * 4 + 0][wrow] = make_float2(w4.x, w4.x);
            Ws2[wk + q * 4 + 1][wrow] = make_float2(w4.y, w4.y);
            Ws2[wk + q * 4 + 2][wrow] = make_float2(w4.z, w4.z);
            Ws2[wk + q * 4 + 3][wrow] = make_float2(w4.w, w4.w);
        }
        // stage X
        *(float4*)&Xs[xr][xc]     = *(const float4*)&X[(k0 + xr) * NB + b0 + xc];
        *(float4*)&Xs[xr][xc + 4] = *(const float4*)&X[(k0 + xr) * NB + b0 + xc + 4];
        __syncthreads();
#pragma unroll
        for (int kk = 0; kk < BK; kk++) {
            unsigned long long wv[TJ];
#pragma unroll
            for (int q = 0; q < TJ / 2; q++) {
                ulonglong2 t = *(const ulonglong2*)&Ws2[kk][ty * TJ + q * 2];
                wv[q * 2] = t.x; wv[q * 2 + 1] = t.y;
            }
            ulonglong2 x01 = *(const ulonglong2*)&Xs[kk][tx * 8];
            ulonglong2 x23 = *(const ulonglong2*)&Xs[kk][tx * 8 + 4];
            unsigned long long xv[4] = {x01.x, x01.y, x23.x, x23.y};
#pragma unroll
            for (int i = 0; i < TJ; i++)
#pragma unroll
                for (int p = 0; p < 4; p++)
                    acc[i][p] = ffma2(wv[i], xv[p], acc[i][p]);
        }
        __syncthreads();
    }

    int bb = b0 + tx * 8;
#pragma unroll
    for (int i = 0; i < TJ; i++) {
        int j = ty * TJ + i;
        if (j >= M) continue;
        float bj = bias[j];
        float o[8];
#pragma unroll
        for (int p = 0; p < 4; p++) {
            F2U u; u.u = acc[i][p];
            o[2 * p]     = u.f.x + bj;
            o[2 * p + 1] = u.f.y + bj;
        }
        if (act) {
#pragma unroll
            for (int e = 0; e < 8; e++) o[e] = tanhf_fast(o[e]);
        }
        *(float4*)&C[j * NB + bb]     = make_float4(o[0], o[1], o[2], o[3]);
        *(float4*)&C[j * NB + bb + 4] = make_float4(o[4], o[5], o[6], o[7]);
    }
}

// Fused pair of big GEMMs: y=0 -> Hf = tanh(WH.hist0+bH), y=1 -> Lf = tanh(WL.hist1+bL)
__global__ __launch_bounds__(256) void gemm_dual(const float* __restrict__ Wa,
                                                 const float* __restrict__ ba,
                                                 const float* __restrict__ Wb,
                                                 const float* __restrict__ bb) {
    int y = blockIdx.y;
    const float* W    = y ? Wb : Wa;
    const float* bias = y ? bb : ba;
    const float* X = g_hist + y * 800 * NB;
    float*       C = g_F    + y * 128 * NB;
    gemm_body<8>(W, bias, X, C, 128, 800, 1, blockIdx.x * BN);
}

// selectors for the generic small GEMMs
#define SEL_X_F     0
#define SEL_X_XT    1
#define SEL_C_Z1    0
#define SEL_C_OTHER 1

template<int TJ>
__global__ __launch_bounds__(256) void gemm_act(const float* __restrict__ W,
                                                const float* __restrict__ bias,
                                                int selX, int selC,
                                                int M, int K, int act) {
    const float* X = (selX == SEL_X_F) ? g_F  : g_xT;
    float*       C = (selC == SEL_C_Z1) ? g_z1 : g_other;
    gemm_body<TJ>(W, bias, X, C, M, K, act, blockIdx.x * BN);
}

// ---------------- tail MLP ----------------
__global__ __launch_bounds__(256) void tail_kernel(const float* __restrict__ W2,
                                                   const float* __restrict__ b2,
                                                   const float* __restrict__ W3,
                                                   const float* __restrict__ b3,
                                                   float* __restrict__ out) {
    __shared__ float sW2[3200], sb2[40], sW3[80];
    __shared__ float sb3;
    int tid = threadIdx.x;
    for (int i = tid; i < 3200; i += 256) sW2[i] = W2[i];
    if (tid < 40) sb2[tid] = b2[tid];
    if (tid < 80) sW3[tid] = W3[tid];
    if (tid == 0) sb3 = b3[0];
    __syncthreads();

    int b = blockIdx.x * 256 + tid;
    float acc[40];
#pragma unroll
    for (int j = 0; j < 40; j++) acc[j] = sb2[j];
    for (int i = 0; i < 80; i++) {
        float v = g_z1[i * NB + b];
#pragma unroll
        for (int j = 0; j < 40; j++) acc[j] = fmaf(sW2[j * 80 + i], v, acc[j]);
    }
    float o = sb3;
#pragma unroll
    for (int j = 0; j < 40; j++) o = fmaf(sW3[j], tanhf_fast(acc[j]), o);
#pragma unroll
    for (int i = 0; i < 40; i++) o = fmaf(sW3[40 + i], g_other[i * NB + b], o);
    out[b] = sigf(o);
}

// ---------------- launch ----------------
extern "C" void kernel_launch(void* const* d_in, const int* in_sizes, int n_in,
                              void* d_out, int out_size) {
    const float* x  = (const float*)d_in[0];
    WPtrs wp;
    for (int i = 0; i < 16; i++) wp.p[i] = (const float*)d_in[1 + i];
    const float* Wp = (const float*)d_in[17];
    const float* bp = (const float*)d_in[18];
    const float* WH = (const float*)d_in[19];
    const float* bH = (const float*)d_in[20];
    const float* WL = (const float*)d_in[21];
    const float* bL = (const float*)d_in[22];
    const float* W1 = (const float*)d_in[23];
    const float* b1 = (const float*)d_in[24];
    const float* W2 = (const float*)d_in[25];
    const float* b2 = (const float*)d_in[26];
    const float* W3 = (const float*)d_in[27];
    const float* b3 = (const float*)d_in[28];

    prep_kernel<<<1, 256>>>(wp);
    transpose_x<<<dim3(NB / 32, 13), dim3(32, 8)>>>(x);
    gemm_act<4><<<dim3(NB / BN, 1), 256>>>(Wp, bp, SEL_X_XT, SEL_C_OTHER, 40, 400, 0);
    lstm_kernel<<<512, 128>>>();
    gemm_dual<<<dim3(NB / BN, 2), 256>>>(WH, bH, WL, bL);
    gemm_act<8><<<dim3(NB / BN, 1), 256>>>(W1, b1, SEL_X_F, SEL_C_Z1, 80, 256, 1);
    tail_kernel<<<NB / 256, 256>>>(W2, b2, W3, b3, (float*)d_out);
}